// round 15
// baseline (speedup 1.0000x reference)
#include <cuda_runtime.h>
#include <cuda_bf16.h>
#include <cstdint>

#define Bn 16
#define Tn 2048
#define Cn 1024
#define Hn 64
#define LD 72          // padded stride used only by qkv kernel

// ---------------- static scratch ----------------
__device__ __nv_bfloat16 g_qh[(size_t)Bn * Tn * Hn];
__device__ __nv_bfloat16 g_ql[(size_t)Bn * Tn * Hn];
__device__ __nv_bfloat16 g_kh[(size_t)Bn * Tn * Hn];
__device__ __nv_bfloat16 g_kl[(size_t)Bn * Tn * Hn];
__device__ __nv_bfloat16 g_vh[(size_t)Bn * Hn * Tn];   // transposed [b][d][t]
__device__ __nv_bfloat16 g_vl[(size_t)Bn * Hn * Tn];
__device__ __nv_bfloat16 g_v2h[(size_t)Bn * Hn * Tn];  // v' = sc * v
__device__ __nv_bfloat16 g_v2l[(size_t)Bn * Hn * Tn];
__device__ __nv_bfloat16 g_wh[3 * Hn * Cn];            // W^T split hi: [mat][n][k]
__device__ __nv_bfloat16 g_wl[3 * Hn * Cn];
__device__ float g_z[(size_t)Bn * 32 * Tn];            // per-(b, 64-row tile) column sumexp
__device__ float g_sc[Bn * Tn];                        // 1 / sum z
__device__ float g_opart[(size_t)2 * Bn * Tn * Hn];    // split-s partials (16MB)

// ---------------- helpers ----------------
__device__ __forceinline__ uint32_t smem_u32(const void* p) {
    uint32_t a;
    asm("{ .reg .u64 t; cvta.to.shared.u64 t, %1; cvt.u32.u64 %0, t; }" : "=r"(a) : "l"(p));
    return a;
}
#define CPA16(saddr, gptr) \
    asm volatile("cp.async.cg.shared.global [%0], [%1], 16;" :: "r"((uint32_t)(saddr)), "l"(gptr))
#define CPA_COMMIT() asm volatile("cp.async.commit_group;" ::: "memory")
#define CPA_WAIT0()  asm volatile("cp.async.wait_group 0;" ::: "memory")
#define CPA_WAIT1()  asm volatile("cp.async.wait_group 1;" ::: "memory")
__device__ __forceinline__ void ldsm_x4(uint32_t& r0, uint32_t& r1, uint32_t& r2, uint32_t& r3, uint32_t a) {
    asm volatile("ldmatrix.sync.aligned.m8n8.x4.shared.b16 {%0,%1,%2,%3}, [%4];"
                 : "=r"(r0), "=r"(r1), "=r"(r2), "=r"(r3) : "r"(a));
}
__device__ __forceinline__ void mma_bf16(float* c, uint32_t a0, uint32_t a1, uint32_t a2, uint32_t a3,
                                         uint32_t b0, uint32_t b1) {
    asm volatile("mma.sync.aligned.m16n8k16.row.col.f32.bf16.bf16.f32 "
                 "{%0,%1,%2,%3},{%4,%5,%6,%7},{%8,%9},{%0,%1,%2,%3};"
                 : "+f"(c[0]), "+f"(c[1]), "+f"(c[2]), "+f"(c[3])
                 : "r"(a0), "r"(a1), "r"(a2), "r"(a3), "r"(b0), "r"(b1));
}
__device__ __forceinline__ float fast_exp(float x) {
    float y = fmaxf(x * 1.4426950408889634f, -126.0f);
    float z = y + 12582912.0f;
    int   i = __float_as_int(z) - 0x4B400000;
    float f = y - (z - 12582912.0f);
    float p = 1.3333558146428443e-3f;
    p = fmaf(p, f, 9.618129107628477e-3f);
    p = fmaf(p, f, 5.550410866482158e-2f);
    p = fmaf(p, f, 2.402265069591007e-1f);
    p = fmaf(p, f, 6.931471805599453e-1f);
    p = fmaf(p, f, 1.0f);
    return __int_as_float(__float_as_int(p) + (i << 23));
}
// Packed pair split: hw = {hi=bf16(v1), lo=bf16(v0)}, lw = residual pair.
__device__ __forceinline__ void split2x2(float v0, float v1, uint32_t& hw, uint32_t& lw) {
    asm("cvt.rn.bf16x2.f32 %0, %1, %2;" : "=r"(hw) : "f"(v1), "f"(v0));
    float r0 = __uint_as_float(hw << 16);
    float r1 = __uint_as_float(hw & 0xFFFF0000u);
    asm("cvt.rn.bf16x2.f32 %0, %1, %2;" : "=r"(lw) : "f"(v1 - r1), "f"(v0 - r0));
}
// XOR swizzles (16B-unit granularity)
#define SW128(o) ((o) ^ (((o) >> 3) & 0x70))   // 128B rows
#define SW256(o) ((o) ^ (((o) >> 4) & 0x70))   // 256B rows

// ================= K0: one-time W split+transpose =================
__global__ __launch_bounds__(256) void wsplit_kernel(
    const float* __restrict__ Wq, const float* __restrict__ Wk, const float* __restrict__ Wv)
{
    int idx = blockIdx.x * 256 + threadIdx.x;
    int n   = idx & 63;
    int k2  = (idx >> 6) & 511;
    int mat = idx >> 15;
    const float* W = (mat == 0) ? Wq : (mat == 1) ? Wk : Wv;
    float w0 = W[(size_t)(2 * k2)     * Hn + n];
    float w1 = W[(size_t)(2 * k2 + 1) * Hn + n];
    uint32_t hw, lw;
    split2x2(w0, w1, hw, lw);
    size_t o = ((size_t)(mat * 64 + n) * 512) + k2;
    ((uint32_t*)g_wh)[o] = hw;
    ((uint32_t*)g_wl)[o] = lw;
}

// ================= K1: QKV projection (x register-prefetch pipeline) =================
#define QK_SMEM ((128 * LD + 128 * LD + 64 * LD + 64 * LD) * 2)
__global__ __launch_bounds__(256, 2) void qkv_kernel(
    const float* __restrict__ x,
    const float* __restrict__ bq, const float* __restrict__ bk, const float* __restrict__ bv)
{
    extern __shared__ char sm[];
    __nv_bfloat16* Ah = (__nv_bfloat16*)sm;
    __nv_bfloat16* Al = Ah + 128 * LD;
    __nv_bfloat16* Bh = Al + 128 * LD;
    __nv_bfloat16* Bl = Bh + 64 * LD;
    const int tid = threadIdx.x, lane = tid & 31, wid = tid >> 5;
    const int wm = wid & 3, wn = wid >> 2;
    const int bid = blockIdx.x;
    const int mat = bid % 3;
    const int mb = (bid / 3) * 128;
    const float* bp = (mat == 0) ? bq : (mat == 1) ? bk : bv;

    const uint32_t sAh = smem_u32(Ah), sAl = smem_u32(Al);
    const uint32_t sBh = smem_u32(Bh), sBl = smem_u32(Bl);
    const int lr = lane & 15, lc = (lane & 16) >> 1;
    const int br = (lane & 7) + ((lane & 16) >> 1), bc = lane & 8;
    const uint4* wh4 = (const uint4*)g_wh;
    const uint4* wl4 = (const uint4*)g_wl;
    // per-thread staging coords
    const int arow = tid >> 4, ac4 = (tid & 15) * 4;     // + i*16 rows

    float acc[2][4][4];
    #pragma unroll
    for (int m = 0; m < 2; m++)
        #pragma unroll
        for (int j = 0; j < 4; j++)
            #pragma unroll
            for (int e = 0; e < 4; e++) acc[m][j][e] = 0.0f;

    // preload chunk 0 x into registers
    float4 xr[8];
    #pragma unroll
    for (int i = 0; i < 8; i++)
        xr[i] = *(const float4*)(x + (size_t)(mb + arow + i * 16) * Cn + ac4);

    for (int ch = 0; ch < 16; ch++) {
        const int k0c = ch * 64;
        // W staging (async)
        #pragma unroll
        for (int i = 0; i < 2; i++) {
            int idx = tid + i * 256;
            int row = idx >> 3, u = idx & 7;
            size_t src = (size_t)(mat * 64 + row) * 128 + (k0c >> 3) + u;
            CPA16(sBh + (uint32_t)((row * LD + u * 8) * 2), wh4 + src);
            CPA16(sBl + (uint32_t)((row * LD + u * 8) * 2), wl4 + src);
        }
        CPA_COMMIT();
        // convert prefetched x -> A smem
        #pragma unroll
        for (int i = 0; i < 8; i++) {
            float4 v = xr[i];
            uint32_t h01, l01, h23, l23;
            split2x2(v.x, v.y, h01, l01);
            split2x2(v.z, v.w, h23, l23);
            int row = arow + i * 16;
            *(uint2*)&Ah[row * LD + ac4] = make_uint2(h01, h23);
            *(uint2*)&Al[row * LD + ac4] = make_uint2(l01, l23);
        }
        // prefetch next chunk's x (latency hidden behind MMA below)
        if (ch < 15) {
            #pragma unroll
            for (int i = 0; i < 8; i++)
                xr[i] = *(const float4*)(x + (size_t)(mb + arow + i * 16) * Cn + k0c + 64 + ac4);
        }
        CPA_WAIT0();
        __syncthreads();
        #pragma unroll
        for (int ks = 0; ks < 4; ks++) {
            const int k0 = ks * 16;
            uint32_t ah[2][4], al[2][4], bh[2][4], bl[2][4];
            #pragma unroll
            for (int m = 0; m < 2; m++) {
                uint32_t ra = (uint32_t)(((wm * 32 + m * 16 + lr) * LD + k0 + lc) * 2);
                ldsm_x4(ah[m][0], ah[m][1], ah[m][2], ah[m][3], sAh + ra);
                ldsm_x4(al[m][0], al[m][1], al[m][2], al[m][3], sAl + ra);
            }
            #pragma unroll
            for (int g = 0; g < 2; g++) {
                uint32_t rb = (uint32_t)(((wn * 32 + g * 16 + br) * LD + k0 + bc) * 2);
                ldsm_x4(bh[g][0], bh[g][1], bh[g][2], bh[g][3], sBh + rb);
                ldsm_x4(bl[g][0], bl[g][1], bl[g][2], bl[g][3], sBl + rb);
            }
            #pragma unroll
            for (int m = 0; m < 2; m++)
                #pragma unroll
                for (int j = 0; j < 4; j++) {
                    uint32_t b0h = bh[j >> 1][(j & 1) * 2], b1h = bh[j >> 1][(j & 1) * 2 + 1];
                    uint32_t b0l = bl[j >> 1][(j & 1) * 2], b1l = bl[j >> 1][(j & 1) * 2 + 1];
                    mma_bf16(acc[m][j], ah[m][0], ah[m][1], ah[m][2], ah[m][3], b0h, b1h);
                    mma_bf16(acc[m][j], al[m][0], al[m][1], al[m][2], al[m][3], b0h, b1h);
                    mma_bf16(acc[m][j], ah[m][0], ah[m][1], ah[m][2], ah[m][3], b0l, b1l);
                }
        }
        __syncthreads();
    }

    const int quad = lane >> 2, pair = lane & 3;
    const int b = mb >> 11, tloc0 = mb & 2047;
    if (mat < 2) {
        uint32_t* dh = (uint32_t*)(mat == 0 ? g_qh : g_kh);
        uint32_t* dl = (uint32_t*)(mat == 0 ? g_ql : g_kl);
        #pragma unroll
        for (int m = 0; m < 2; m++)
            #pragma unroll
            for (int rr = 0; rr < 2; rr++)
                #pragma unroll
                for (int j = 0; j < 4; j++) {
                    int row = wm * 32 + m * 16 + rr * 8 + quad;
                    int col = wn * 32 + j * 8 + 2 * pair;
                    float v0 = acc[m][j][rr * 2]     + bp[col];
                    float v1 = acc[m][j][rr * 2 + 1] + bp[col + 1];
                    uint32_t hw, lw;
                    split2x2(v0, v1, hw, lw);
                    size_t o = (size_t)(mb + row) * 32 + (col >> 1);
                    dh[o] = hw;
                    dl[o] = lw;
                }
    } else {
        __nv_bfloat16* Th = Ah;
        __nv_bfloat16* Tl = Al;
        #pragma unroll
        for (int m = 0; m < 2; m++)
            #pragma unroll
            for (int rr = 0; rr < 2; rr++)
                #pragma unroll
                for (int j = 0; j < 4; j++) {
                    int row = wm * 32 + m * 16 + rr * 8 + quad;
                    int col = wn * 32 + j * 8 + 2 * pair;
                    float v0 = acc[m][j][rr * 2]     + bp[col];
                    float v1 = acc[m][j][rr * 2 + 1] + bp[col + 1];
                    uint32_t hw, lw;
                    split2x2(v0, v1, hw, lw);
                    Th[col * 132 + row]       = __ushort_as_bfloat16((unsigned short)(hw & 0xFFFF));
                    Th[(col + 1) * 132 + row] = __ushort_as_bfloat16((unsigned short)(hw >> 16));
                    Tl[col * 132 + row]       = __ushort_as_bfloat16((unsigned short)(lw & 0xFFFF));
                    Tl[(col + 1) * 132 + row] = __ushort_as_bfloat16((unsigned short)(lw >> 16));
                }
        __syncthreads();
        uint32_t* vh32 = (uint32_t*)g_vh;
        uint32_t* vl32 = (uint32_t*)g_vl;
        const uint32_t* th32 = (const uint32_t*)Th;
        const uint32_t* tl32 = (const uint32_t*)Tl;
        #pragma unroll
        for (int i = 0; i < 16; i++) {
            int idx = tid + i * 256;
            int d = idx >> 6, t2 = idx & 63;
            size_t o = (size_t)(b * 64 + d) * 1024 + (tloc0 >> 1) + t2;
            vh32[o] = th32[d * 66 + t2];
            vl32[o] = tl32[d * 66 + t2];
        }
    }
}

// ================= pass1: 64x128 S tile -> column sumexp z (cp.async staging) =================
#define P1_QH 0
#define P1_QL 8192
#define P1_KH 16384
#define P1_KL 32768
#define P1_ZB 49152
#define P1_SMEM (49152 + 1024)
__global__ __launch_bounds__(256, 2) void pass1_kernel()
{
    const int bt = blockIdx.x;
    const int bs = blockIdx.y;
    const int b  = blockIdx.z;
    const int bsMax = ((bt + 1) * 64 - 1) >> 7;
    if (bs > bsMax) return;

    extern __shared__ char sm[];
    const uint32_t sb = smem_u32(sm);
    const int tid = threadIdx.x, lane = tid & 31, wid = tid >> 5;
    const int wm = wid & 1, wn = wid >> 1;
    const int lr = lane & 15, lc = (lane & 16) >> 1;
    const int br = (lane & 7) + ((lane & 16) >> 1), bc = lane & 8;
    const int quad = lane >> 2, pair = lane & 3;

    {
        const uint4* qh = (const uint4*)(g_qh + ((size_t)b * Tn + bt * 64) * Hn);
        const uint4* ql = (const uint4*)(g_ql + ((size_t)b * Tn + bt * 64) * Hn);
        #pragma unroll
        for (int i = 0; i < 2; i++) {
            int idx = tid + i * 256;
            int row = idx >> 3, u = idx & 7;
            uint32_t off = SW128((uint32_t)(row * 128 + u * 16));
            CPA16(sb + P1_QH + off, qh + idx);
            CPA16(sb + P1_QL + off, ql + idx);
        }
        const uint4* kh = (const uint4*)(g_kh + ((size_t)b * Tn + bs * 128) * Hn);
        const uint4* kl = (const uint4*)(g_kl + ((size_t)b * Tn + bs * 128) * Hn);
        #pragma unroll
        for (int i = 0; i < 4; i++) {
            int idx = tid + i * 256;
            int row = idx >> 3, u = idx & 7;
            uint32_t off = SW128((uint32_t)(row * 128 + u * 16));
            CPA16(sb + P1_KH + off, kh + idx);
            CPA16(sb + P1_KL + off, kl + idx);
        }
        CPA_COMMIT();
        CPA_WAIT0();
    }
    __syncthreads();

    float acc[2][4][4];
    #pragma unroll
    for (int m = 0; m < 2; m++)
        #pragma unroll
        for (int j = 0; j < 4; j++)
            #pragma unroll
            for (int e = 0; e < 4; e++) acc[m][j][e] = 0.0f;

    #pragma unroll
    for (int ks = 0; ks < 4; ks++) {
        const int k0 = ks * 16;
        uint32_t ah[2][4], al[2][4], bh[2][4], bl[2][4];
        #pragma unroll
        for (int m = 0; m < 2; m++) {
            uint32_t ra = SW128((uint32_t)((wm * 32 + m * 16 + lr) * 128 + (k0 + lc) * 2));
            ldsm_x4(ah[m][0], ah[m][1], ah[m][2], ah[m][3], sb + P1_QH + ra);
            ldsm_x4(al[m][0], al[m][1], al[m][2], al[m][3], sb + P1_QL + ra);
        }
        #pragma unroll
        for (int g = 0; g < 2; g++) {
            uint32_t rb = SW128((uint32_t)((wn * 32 + g * 16 + br) * 128 + (k0 + bc) * 2));
            ldsm_x4(bh[g][0], bh[g][1], bh[g][2], bh[g][3], sb + P1_KH + rb);
            ldsm_x4(bl[g][0], bl[g][1], bl[g][2], bl[g][3], sb + P1_KL + rb);
        }
        #pragma unroll
        for (int m = 0; m < 2; m++)
            #pragma unroll
            for (int j = 0; j < 4; j++) {
                uint32_t b0h = bh[j >> 1][(j & 1) * 2], b1h = bh[j >> 1][(j & 1) * 2 + 1];
                uint32_t b0l = bl[j >> 1][(j & 1) * 2], b1l = bl[j >> 1][(j & 1) * 2 + 1];
                mma_bf16(acc[m][j], ah[m][0], ah[m][1], ah[m][2], ah[m][3], b0h, b1h);
                mma_bf16(acc[m][j], al[m][0], al[m][1], al[m][2], al[m][3], b0h, b1h);
                mma_bf16(acc[m][j], ah[m][0], ah[m][1], ah[m][2], ah[m][3], b0l, b1l);
            }
    }

    float* zbuf = (float*)(sm + P1_ZB);
    #pragma unroll
    for (int j = 0; j < 4; j++) {
        float z0 = 0.0f, z1 = 0.0f;
        int cloc = wn * 32 + j * 8 + 2 * pair;
        int scol = bs * 128 + cloc;
        #pragma unroll
        for (int m = 0; m < 2; m++)
            #pragma unroll
            for (int rr = 0; rr < 2; rr++) {
                int trow = bt * 64 + wm * 32 + m * 16 + rr * 8 + quad;
                z0 += (scol     <= trow) ? fast_exp(acc[m][j][rr * 2])     : 0.0f;
                z1 += (scol + 1 <= trow) ? fast_exp(acc[m][j][rr * 2 + 1]) : 0.0f;
            }
        #pragma unroll
        for (int off = 4; off < 32; off <<= 1) {
            z0 += __shfl_xor_sync(0xffffffffu, z0, off);
            z1 += __shfl_xor_sync(0xffffffffu, z1, off);
        }
        if (quad == 0) {
            zbuf[wm * 128 + cloc]     = z0;
            zbuf[wm * 128 + cloc + 1] = z1;
        }
    }
    __syncthreads();
    if (tid < 128)
        g_z[((size_t)b * 32 + bt) * Tn + bs * 128 + tid] = zbuf[tid] + zbuf[128 + tid];
}

// ================= cmerge: sc[b][s] = 1 / sum_bt z (4 threads per s) =================
__global__ __launch_bounds__(256) void cmerge_kernel()
{
    int gid = blockIdx.x * 256 + threadIdx.x;   // 512 blocks * 256 = 4 per (b,s)
    int sub = gid & 3;
    int idx = gid >> 2;                         // b*2048 + s
    int b = idx >> 11, s = idx & 2047;
    int bt0 = s >> 6;
    float z = 0.0f;
    for (int bt = bt0 + ((sub - bt0) & 3); bt < 32; bt += 4)
        z += g_z[((size_t)b * 32 + bt) * Tn + s];
    z += __shfl_xor_sync(0xffffffffu, z, 1);
    z += __shfl_xor_sync(0xffffffffu, z, 2);
    if (sub == 0) g_sc[idx] = 1.0f / z;
}

// ================= vscale: v' = sc[t] * v =================
__global__ __launch_bounds__(256) void vscale_kernel()
{
    int idx = blockIdx.x * 256 + threadIdx.x;
    int t2 = idx & 1023;
    int b  = idx >> 16;
    uint32_t hw = ((const uint32_t*)g_vh)[idx];
    uint32_t lw = ((const uint32_t*)g_vl)[idx];
    __nv_bfloat162 hb = *(__nv_bfloat162*)&hw;
    __nv_bfloat162 lb = *(__nv_bfloat162*)&lw;
    float sc0 = g_sc[b * Tn + 2 * t2];
    float sc1 = g_sc[b * Tn + 2 * t2 + 1];
    float v0 = (__low2float(hb)  + __low2float(lb))  * sc0;
    float v1 = (__high2float(hb) + __high2float(lb)) * sc1;
    uint32_t oh, ol;
    split2x2(v0, v1, oh, ol);
    ((uint32_t*)g_v2h)[idx] = oh;
    ((uint32_t*)g_v2l)[idx] = ol;
}

// ================= pass2: register P-frag reuse + split-wait cp.async =================
#define P2_QH 0
#define P2_QL 8192
#define P2_KH 16384
#define P2_KL 32768
#define P2_VH 49152
#define P2_VL 65536
#define P2_RED 81920
#define P2_SMEM (81920 + 64 * 66 * 4)
__global__ __launch_bounds__(256, 2) void pass2_kernel()
{
    const int bt = 31 - blockIdx.x;
    const int b  = blockIdx.y;
    const int sp = blockIdx.z;
    const int bsMax = ((bt + 1) * 64 - 1) >> 7;
    const int sBeg = sp * 8;
    const int sEnd = min(bsMax + 1, sBeg + 8);
    if (sBeg >= sEnd) return;

    extern __shared__ char sm[];
    const uint32_t sb = smem_u32(sm);
    const int tid = threadIdx.x, lane = tid & 31, wid = tid >> 5;
    const int wm = wid & 3, ws = wid >> 2;
    const int lr = lane & 15, lc = (lane & 16) >> 1;
    const int br = (lane & 7) + ((lane & 16) >> 1), bc = lane & 8;
    const int quad = lane >> 2, pair = lane & 3;

    {
        const uint4* qh = (const uint4*)(g_qh + ((size_t)b * Tn + bt * 64) * Hn);
        const uint4* ql = (const uint4*)(g_ql + ((size_t)b * Tn + bt * 64) * Hn);
        #pragma unroll
        for (int i = 0; i < 2; i++) {
            int idx = tid + i * 256;
            int row = idx >> 3, u = idx & 7;
            uint32_t off = SW128((uint32_t)(row * 128 + u * 16));
            CPA16(sb + P2_QH + off, qh + idx);
            CPA16(sb + P2_QL + off, ql + idx);
        }
        CPA_COMMIT();
    }

    const uint4* gKh = (const uint4*)(g_kh + (size_t)b * Tn * Hn);
    const uint4* gKl = (const uint4*)(g_kl + (size_t)b * Tn * Hn);
    const uint4* gVh4 = (const uint4*)(g_v2h + (size_t)b * Hn * Tn);
    const uint4* gVl4 = (const uint4*)(g_v2l + (size_t)b * Hn * Tn);

    float accO[8][4];
    #pragma unroll
    for (int g = 0; g < 8; g++)
        #pragma unroll
        for (int e = 0; e < 4; e++) accO[g][e] = 0.0f;

    for (int bs = sBeg; bs < sEnd; bs++) {
        __syncthreads();
        // K group
        #pragma unroll
        for (int i = 0; i < 4; i++) {
            int idx = tid + i * 256;
            int row = idx >> 3, u = idx & 7;
            uint32_t off = SW128((uint32_t)(row * 128 + u * 16));
            CPA16(sb + P2_KH + off, gKh + bs * 1024 + idx);
            CPA16(sb + P2_KL + off, gKl + bs * 1024 + idx);
        }
        CPA_COMMIT();
        // V group
        #pragma unroll
        for (int i = 0; i < 4; i++) {
            int idx = tid + i * 256;
            int d = idx >> 4, c = idx & 15;
            uint32_t off = SW256((uint32_t)(d * 256 + c * 16));
            CPA16(sb + P2_VH + off, gVh4 + (size_t)d * 256 + bs * 16 + c);
            CPA16(sb + P2_VL + off, gVl4 + (size_t)d * 256 + bs * 16 + c);
        }
        CPA_COMMIT();
        CPA_WAIT1();            // K (and Q on first iter) landed; V may still fly
        __syncthreads();

        float acc[8][4];
        #pragma unroll
        for (int j = 0; j < 8; j++)
            #pragma unroll
            for (int e = 0; e < 4; e++) acc[j][e] = 0.0f;
        #pragma unroll
        for (int ks = 0; ks < 4; ks++) {
            const int k0 = ks * 16;
            uint32_t ah[4], al[4];
            uint32_t ra = SW128((uint32_t)((wm * 16 + lr) * 128 + (k0 + lc) * 2));
            ldsm_x4(ah[0], ah[1], ah[2], ah[3], sb + P2_QH + ra);
            ldsm_x4(al[0], al[1], al[2], al[3], sb + P2_QL + ra);
            #pragma unroll
            for (int g16 = 0; g16 < 4; g16++) {
                uint32_t bh[4], bl[4];
                uint32_t rb = SW128((uint32_t)((ws * 64 + g16 * 16 + br) * 128 + (k0 + bc) * 2));
                ldsm_x4(bh[0], bh[1], bh[2], bh[3], sb + P2_KH + rb);
                ldsm_x4(bl[0], bl[1], bl[2], bl[3], sb + P2_KL + rb);
                #pragma unroll
                for (int jj = 0; jj < 2; jj++) {
                    int j = g16 * 2 + jj;
                    uint32_t b0h = bh[jj * 2], b1h = bh[jj * 2 + 1];
                    uint32_t b0l = bl[jj * 2], b1l = bl[jj * 2 + 1];
                    mma_bf16(acc[j], ah[0], ah[1], ah[2], ah[3], b0h, b1h);
                    mma_bf16(acc[j], al[0], al[1], al[2], al[3], b0h, b1h);
                    mma_bf16(acc[j], ah[0], ah[1], ah[2], ah[3], b0l, b1l);
                }
            }
        }
        CPA_WAIT0();            // V landed (overlapped with S-MMA above)
        __syncthreads();

        const int trow0 = bt * 64 + wm * 16 + quad;
        const int trow1 = trow0 + 8;
        #pragma unroll
        for (int kk = 0; kk < 4; kk++) {
            const int j0 = 2 * kk;
            uint32_t pah[4], pal[4];
            {
                int c0 = bs * 128 + ws * 64 + j0 * 8 + 2 * pair;
                float p0 = (c0     <= trow0) ? fast_exp(acc[j0][0]) : 0.0f;
                float p1 = (c0 + 1 <= trow0) ? fast_exp(acc[j0][1]) : 0.0f;
                split2x2(p0, p1, pah[0], pal[0]);
                p0 = (c0     <= trow1) ? fast_exp(acc[j0][2]) : 0.0f;
                p1 = (c0 + 1 <= trow1) ? fast_exp(acc[j0][3]) : 0.0f;
                split2x2(p0, p1, pah[1], pal[1]);
                int c1 = c0 + 8;
                p0 = (c1     <= trow0) ? fast_exp(acc[j0 + 1][0]) : 0.0f;
                p1 = (c1 + 1 <= trow0) ? fast_exp(acc[j0 + 1][1]) : 0.0f;
                split2x2(p0, p1, pah[2], pal[2]);
                p0 = (c1     <= trow1) ? fast_exp(acc[j0 + 1][2]) : 0.0f;
                p1 = (c1 + 1 <= trow1) ? fast_exp(acc[j0 + 1][3]) : 0.0f;
                split2x2(p0, p1, pah[3], pal[3]);
            }
            const int k0g = ws * 64 + kk * 16;
            #pragma unroll
            for (int g16 = 0; g16 < 4; g16++) {
                uint32_t vh[4], vl[4];
                uint32_t rb = SW256((uint32_t)((g16 * 16 + br) * 256 + (k0g + bc) * 2));
                ldsm_x4(vh[0], vh[1], vh[2], vh[3], sb + P2_VH + rb);
                ldsm_x4(vl[0], vl[1], vl[2], vl[3], sb + P2_VL + rb);
                #pragma unroll
                for (int gg = 0; gg < 2; gg++) {
                    int g = g16 * 2 + gg;
                    uint32_t b0h = vh[gg * 2], b1h = vh[gg * 2 + 1];
                    uint32_t b0l = vl[gg * 2], b1l = vl[gg * 2 + 1];
                    mma_bf16(accO[g], pah[0], pah[1], pah[2], pah[3], b0h, b1h);
                    mma_bf16(accO[g], pal[0], pal[1], pal[2], pal[3], b0h, b1h);
                    mma_bf16(accO[g], pah[0], pah[1], pah[2], pah[3], b0l, b1l);
                }
            }
        }
    }

    float* red = (float*)(sm + P2_RED);
    __syncthreads();
    if (ws == 1) {
        #pragma unroll
        for (int g = 0; g < 8; g++)
            #pragma unroll
            for (int rr = 0; rr < 2; rr++) {
                int row = wm * 16 + rr * 8 + quad;
                int col = g * 8 + 2 * pair;
                *(float2*)&red[row * 66 + col] =
                    make_float2(accO[g][rr * 2], accO[g][rr * 2 + 1]);
            }
    }
    __syncthreads();
    if (ws == 0) {
        #pragma unroll
        for (int g = 0; g < 8; g++)
            #pragma unroll
            for (int rr = 0; rr < 2; rr++) {
                int row = wm * 16 + rr * 8 + quad;
                int col = g * 8 + 2 * pair;
                float2 r = *(const float2*)&red[row * 66 + col];
                float2 v = make_float2(accO[g][rr * 2] + r.x, accO[g][rr * 2 + 1] + r.y);
                *(float2*)(g_opart + (((size_t)sp * Bn + b) * Tn + bt * 64 + row) * Hn + col) = v;
            }
    }
}

// ================= reduce =================
__global__ __launch_bounds__(256) void reduce_kernel(float* __restrict__ out)
{
    int idx = blockIdx.x * 256 + threadIdx.x;
    int d4 = idx & 15;
    int t  = (idx >> 4) & 2047;
    int b  = idx >> 15;
    float4 s = *(const float4*)(g_opart + (((size_t)b) * Tn + t) * Hn + d4 * 4);
    if (t >= 1024) {
        float4 v = *(const float4*)(g_opart + (((size_t)Bn + b) * Tn + t) * Hn + d4 * 4);
        s.x += v.x; s.y += v.y; s.z += v.z; s.w += v.w;
    }
    *(float4*)(out + ((size_t)b * Tn + t) * Hn + d4 * 4) = s;
}

extern "C" void kernel_launch(void* const* d_in, const int* in_sizes, int n_in,
                              void* d_out, int out_size)
{
    const float* x  = (const float*)d_in[0];
    const float* Wq = (const float*)d_in[1];
    const float* bq = (const float*)d_in[2];
    const float* Wk = (const float*)d_in[3];
    const float* bk = (const float*)d_in[4];
    const float* Wv = (const float*)d_in[5];
    const float* bv = (const float*)d_in[6];
    float* out = (float*)d_out;

    cudaFuncSetAttribute(qkv_kernel,   cudaFuncAttributeMaxDynamicSharedMemorySize, QK_SMEM);
    cudaFuncSetAttribute(pass1_kernel, cudaFuncAttributeMaxDynamicSharedMemorySize, P1_SMEM);
    cudaFuncSetAttribute(pass2_kernel, cudaFuncAttributeMaxDynamicSharedMemorySize, P2_SMEM);

    wsplit_kernel<<<384, 256>>>(Wq, Wk, Wv);
    qkv_kernel<<<768, 256, QK_SMEM>>>(x, bq, bk, bv);
    pass1_kernel<<<dim3(32, 16, 16), 256, P1_SMEM>>>();
    cmerge_kernel<<<512, 256>>>();
    vscale_kernel<<<4096, 256>>>();
    pass2_kernel<<<dim3(32, 16, 2), 256, P2_SMEM>>>();
    reduce_kernel<<<2048, 256>>>(out);
}

// round 16
// speedup vs baseline: 1.5039x; 1.5039x over previous
#include <cuda_runtime.h>
#include <cuda_bf16.h>
#include <cstdint>

#define Bn 16
#define Tn 2048
#define Cn 1024
#define Hn 64
#define LD 72          // padded stride used only by qkv kernel

// ---------------- static scratch ----------------
__device__ __nv_bfloat16 g_qh[(size_t)Bn * Tn * Hn];
__device__ __nv_bfloat16 g_ql[(size_t)Bn * Tn * Hn];
__device__ __nv_bfloat16 g_kh[(size_t)Bn * Tn * Hn];
__device__ __nv_bfloat16 g_kl[(size_t)Bn * Tn * Hn];
__device__ __nv_bfloat16 g_vh[(size_t)Bn * Hn * Tn];   // transposed [b][d][t]
__device__ __nv_bfloat16 g_vl[(size_t)Bn * Hn * Tn];
__device__ __nv_bfloat16 g_v2h[(size_t)Bn * Hn * Tn];  // v' = sc * v
__device__ __nv_bfloat16 g_v2l[(size_t)Bn * Hn * Tn];
__device__ __nv_bfloat16 g_wh[3 * Hn * Cn];            // W^T split hi: [mat][n][k]
__device__ __nv_bfloat16 g_wl[3 * Hn * Cn];
__device__ float g_z[(size_t)Bn * 32 * Tn];            // per-(b, 64-row tile) column sumexp
__device__ float g_sc[Bn * Tn];                        // 1 / sum z
__device__ float g_opart[(size_t)2 * Bn * Tn * Hn];    // split-s partials (16MB)

// ---------------- helpers ----------------
__device__ __forceinline__ uint32_t smem_u32(const void* p) {
    uint32_t a;
    asm("{ .reg .u64 t; cvta.to.shared.u64 t, %1; cvt.u32.u64 %0, t; }" : "=r"(a) : "l"(p));
    return a;
}
#define CPA16(saddr, gptr) \
    asm volatile("cp.async.cg.shared.global [%0], [%1], 16;" :: "r"((uint32_t)(saddr)), "l"(gptr))
#define CPA_COMMIT() asm volatile("cp.async.commit_group;" ::: "memory")
#define CPA_WAIT0()  asm volatile("cp.async.wait_group 0;" ::: "memory")
#define CPA_WAIT1()  asm volatile("cp.async.wait_group 1;" ::: "memory")
__device__ __forceinline__ void ldsm_x4(uint32_t& r0, uint32_t& r1, uint32_t& r2, uint32_t& r3, uint32_t a) {
    asm volatile("ldmatrix.sync.aligned.m8n8.x4.shared.b16 {%0,%1,%2,%3}, [%4];"
                 : "=r"(r0), "=r"(r1), "=r"(r2), "=r"(r3) : "r"(a));
}
__device__ __forceinline__ void mma_bf16(float* c, uint32_t a0, uint32_t a1, uint32_t a2, uint32_t a3,
                                         uint32_t b0, uint32_t b1) {
    asm volatile("mma.sync.aligned.m16n8k16.row.col.f32.bf16.bf16.f32 "
                 "{%0,%1,%2,%3},{%4,%5,%6,%7},{%8,%9},{%0,%1,%2,%3};"
                 : "+f"(c[0]), "+f"(c[1]), "+f"(c[2]), "+f"(c[3])
                 : "r"(a0), "r"(a1), "r"(a2), "r"(a3), "r"(b0), "r"(b1));
}
__device__ __forceinline__ float fast_exp(float x) {
    float y = fmaxf(x * 1.4426950408889634f, -126.0f);
    float z = y + 12582912.0f;
    int   i = __float_as_int(z) - 0x4B400000;
    float f = y - (z - 12582912.0f);
    float p = 1.3333558146428443e-3f;
    p = fmaf(p, f, 9.618129107628477e-3f);
    p = fmaf(p, f, 5.550410866482158e-2f);
    p = fmaf(p, f, 2.402265069591007e-1f);
    p = fmaf(p, f, 6.931471805599453e-1f);
    p = fmaf(p, f, 1.0f);
    return __int_as_float(__float_as_int(p) + (i << 23));
}
// Packed pair split: hw = {hi=bf16(v1), lo=bf16(v0)}, lw = residual pair.
__device__ __forceinline__ void split2x2(float v0, float v1, uint32_t& hw, uint32_t& lw) {
    asm("cvt.rn.bf16x2.f32 %0, %1, %2;" : "=r"(hw) : "f"(v1), "f"(v0));
    float r0 = __uint_as_float(hw << 16);
    float r1 = __uint_as_float(hw & 0xFFFF0000u);
    asm("cvt.rn.bf16x2.f32 %0, %1, %2;" : "=r"(lw) : "f"(v1 - r1), "f"(v0 - r0));
}
// XOR swizzles (16B-unit granularity)
#define SW128(o) ((o) ^ (((o) >> 3) & 0x70))   // 128B rows
#define SW256(o) ((o) ^ (((o) >> 4) & 0x70))   // 256B rows

// ================= K0: one-time W split+transpose =================
__global__ __launch_bounds__(256) void wsplit_kernel(
    const float* __restrict__ Wq, const float* __restrict__ Wk, const float* __restrict__ Wv)
{
    int idx = blockIdx.x * 256 + threadIdx.x;
    int n   = idx & 63;
    int k2  = (idx >> 6) & 511;
    int mat = idx >> 15;
    const float* W = (mat == 0) ? Wq : (mat == 1) ? Wk : Wv;
    float w0 = W[(size_t)(2 * k2)     * Hn + n];
    float w1 = W[(size_t)(2 * k2 + 1) * Hn + n];
    uint32_t hw, lw;
    split2x2(w0, w1, hw, lw);
    size_t o = ((size_t)(mat * 64 + n) * 512) + k2;
    ((uint32_t*)g_wh)[o] = hw;
    ((uint32_t*)g_wl)[o] = lw;
}

// ================= K1: QKV projection (round-14 version, verified best) =================
#define QK_SMEM ((128 * LD + 128 * LD + 64 * LD + 64 * LD) * 2)
__global__ __launch_bounds__(256, 2) void qkv_kernel(
    const float* __restrict__ x,
    const float* __restrict__ bq, const float* __restrict__ bk, const float* __restrict__ bv)
{
    extern __shared__ char sm[];
    __nv_bfloat16* Ah = (__nv_bfloat16*)sm;
    __nv_bfloat16* Al = Ah + 128 * LD;
    __nv_bfloat16* Bh = Al + 128 * LD;
    __nv_bfloat16* Bl = Bh + 64 * LD;
    const int tid = threadIdx.x, lane = tid & 31, wid = tid >> 5;
    const int wm = wid & 3, wn = wid >> 2;
    const int bid = blockIdx.x;
    const int mat = bid % 3;
    const int mb = (bid / 3) * 128;
    const float* bp = (mat == 0) ? bq : (mat == 1) ? bk : bv;

    const uint32_t sAh = smem_u32(Ah), sAl = smem_u32(Al);
    const uint32_t sBh = smem_u32(Bh), sBl = smem_u32(Bl);
    const int lr = lane & 15, lc = (lane & 16) >> 1;
    const int br = (lane & 7) + ((lane & 16) >> 1), bc = lane & 8;
    const uint4* wh4 = (const uint4*)g_wh;
    const uint4* wl4 = (const uint4*)g_wl;

    float acc[2][4][4];
    #pragma unroll
    for (int m = 0; m < 2; m++)
        #pragma unroll
        for (int j = 0; j < 4; j++)
            #pragma unroll
            for (int e = 0; e < 4; e++) acc[m][j][e] = 0.0f;

    for (int ch = 0; ch < 16; ch++) {
        const int k0c = ch * 64;
        // W staging first (async, overlaps with A conversion below)
        #pragma unroll
        for (int i = 0; i < 2; i++) {
            int idx = tid + i * 256;
            int row = idx >> 3, u = idx & 7;
            size_t src = (size_t)(mat * 64 + row) * 128 + (k0c >> 3) + u;
            CPA16(sBh + (uint32_t)((row * LD + u * 8) * 2), wh4 + src);
            CPA16(sBl + (uint32_t)((row * LD + u * 8) * 2), wl4 + src);
        }
        CPA_COMMIT();
        // A staging: packed pairs, STS.64
        #pragma unroll
        for (int i = 0; i < 8; i++) {
            int idx = tid + i * 256;
            int row = idx >> 4, c4 = (idx & 15) * 4;
            float4 v = *(const float4*)(x + (size_t)(mb + row) * Cn + k0c + c4);
            uint32_t h01, l01, h23, l23;
            split2x2(v.x, v.y, h01, l01);
            split2x2(v.z, v.w, h23, l23);
            *(uint2*)&Ah[row * LD + c4] = make_uint2(h01, h23);
            *(uint2*)&Al[row * LD + c4] = make_uint2(l01, l23);
        }
        CPA_WAIT0();
        __syncthreads();
        #pragma unroll
        for (int ks = 0; ks < 4; ks++) {
            const int k0 = ks * 16;
            uint32_t ah[2][4], al[2][4], bh[2][4], bl[2][4];
            #pragma unroll
            for (int m = 0; m < 2; m++) {
                uint32_t ra = (uint32_t)(((wm * 32 + m * 16 + lr) * LD + k0 + lc) * 2);
                ldsm_x4(ah[m][0], ah[m][1], ah[m][2], ah[m][3], sAh + ra);
                ldsm_x4(al[m][0], al[m][1], al[m][2], al[m][3], sAl + ra);
            }
            #pragma unroll
            for (int g = 0; g < 2; g++) {
                uint32_t rb = (uint32_t)(((wn * 32 + g * 16 + br) * LD + k0 + bc) * 2);
                ldsm_x4(bh[g][0], bh[g][1], bh[g][2], bh[g][3], sBh + rb);
                ldsm_x4(bl[g][0], bl[g][1], bl[g][2], bl[g][3], sBl + rb);
            }
            #pragma unroll
            for (int m = 0; m < 2; m++)
                #pragma unroll
                for (int j = 0; j < 4; j++) {
                    uint32_t b0h = bh[j >> 1][(j & 1) * 2], b1h = bh[j >> 1][(j & 1) * 2 + 1];
                    uint32_t b0l = bl[j >> 1][(j & 1) * 2], b1l = bl[j >> 1][(j & 1) * 2 + 1];
                    mma_bf16(acc[m][j], ah[m][0], ah[m][1], ah[m][2], ah[m][3], b0h, b1h);
                    mma_bf16(acc[m][j], al[m][0], al[m][1], al[m][2], al[m][3], b0h, b1h);
                    mma_bf16(acc[m][j], ah[m][0], ah[m][1], ah[m][2], ah[m][3], b0l, b1l);
                }
        }
        __syncthreads();
    }

    const int quad = lane >> 2, pair = lane & 3;
    const int b = mb >> 11, tloc0 = mb & 2047;
    if (mat < 2) {
        uint32_t* dh = (uint32_t*)(mat == 0 ? g_qh : g_kh);
        uint32_t* dl = (uint32_t*)(mat == 0 ? g_ql : g_kl);
        #pragma unroll
        for (int m = 0; m < 2; m++)
            #pragma unroll
            for (int rr = 0; rr < 2; rr++)
                #pragma unroll
                for (int j = 0; j < 4; j++) {
                    int row = wm * 32 + m * 16 + rr * 8 + quad;
                    int col = wn * 32 + j * 8 + 2 * pair;
                    float v0 = acc[m][j][rr * 2]     + bp[col];
                    float v1 = acc[m][j][rr * 2 + 1] + bp[col + 1];
                    uint32_t hw, lw;
                    split2x2(v0, v1, hw, lw);
                    size_t o = (size_t)(mb + row) * 32 + (col >> 1);
                    dh[o] = hw;
                    dl[o] = lw;
                }
    } else {
        __nv_bfloat16* Th = Ah;
        __nv_bfloat16* Tl = Al;
        #pragma unroll
        for (int m = 0; m < 2; m++)
            #pragma unroll
            for (int rr = 0; rr < 2; rr++)
                #pragma unroll
                for (int j = 0; j < 4; j++) {
                    int row = wm * 32 + m * 16 + rr * 8 + quad;
                    int col = wn * 32 + j * 8 + 2 * pair;
                    float v0 = acc[m][j][rr * 2]     + bp[col];
                    float v1 = acc[m][j][rr * 2 + 1] + bp[col + 1];
                    uint32_t hw, lw;
                    split2x2(v0, v1, hw, lw);
                    Th[col * 132 + row]       = __ushort_as_bfloat16((unsigned short)(hw & 0xFFFF));
                    Th[(col + 1) * 132 + row] = __ushort_as_bfloat16((unsigned short)(hw >> 16));
                    Tl[col * 132 + row]       = __ushort_as_bfloat16((unsigned short)(lw & 0xFFFF));
                    Tl[(col + 1) * 132 + row] = __ushort_as_bfloat16((unsigned short)(lw >> 16));
                }
        __syncthreads();
        uint32_t* vh32 = (uint32_t*)g_vh;
        uint32_t* vl32 = (uint32_t*)g_vl;
        const uint32_t* th32 = (const uint32_t*)Th;
        const uint32_t* tl32 = (const uint32_t*)Tl;
        #pragma unroll
        for (int i = 0; i < 16; i++) {
            int idx = tid + i * 256;
            int d = idx >> 6, t2 = idx & 63;
            size_t o = (size_t)(b * 64 + d) * 1024 + (tloc0 >> 1) + t2;
            vh32[o] = th32[d * 66 + t2];
            vl32[o] = tl32[d * 66 + t2];
        }
    }
}

// ================= pass1: 64x128 S tile -> column sumexp z (cp.async staging) =================
#define P1_QH 0
#define P1_QL 8192
#define P1_KH 16384
#define P1_KL 32768
#define P1_ZB 49152
#define P1_SMEM (49152 + 1024)
__global__ __launch_bounds__(256, 2) void pass1_kernel()
{
    const int bt = blockIdx.x;
    const int bs = blockIdx.y;
    const int b  = blockIdx.z;
    const int bsMax = ((bt + 1) * 64 - 1) >> 7;
    if (bs > bsMax) return;

    extern __shared__ char sm[];
    const uint32_t sb = smem_u32(sm);
    const int tid = threadIdx.x, lane = tid & 31, wid = tid >> 5;
    const int wm = wid & 1, wn = wid >> 1;
    const int lr = lane & 15, lc = (lane & 16) >> 1;
    const int br = (lane & 7) + ((lane & 16) >> 1), bc = lane & 8;
    const int quad = lane >> 2, pair = lane & 3;

    {
        const uint4* qh = (const uint4*)(g_qh + ((size_t)b * Tn + bt * 64) * Hn);
        const uint4* ql = (const uint4*)(g_ql + ((size_t)b * Tn + bt * 64) * Hn);
        #pragma unroll
        for (int i = 0; i < 2; i++) {
            int idx = tid + i * 256;
            int row = idx >> 3, u = idx & 7;
            uint32_t off = SW128((uint32_t)(row * 128 + u * 16));
            CPA16(sb + P1_QH + off, qh + idx);
            CPA16(sb + P1_QL + off, ql + idx);
        }
        const uint4* kh = (const uint4*)(g_kh + ((size_t)b * Tn + bs * 128) * Hn);
        const uint4* kl = (const uint4*)(g_kl + ((size_t)b * Tn + bs * 128) * Hn);
        #pragma unroll
        for (int i = 0; i < 4; i++) {
            int idx = tid + i * 256;
            int row = idx >> 3, u = idx & 7;
            uint32_t off = SW128((uint32_t)(row * 128 + u * 16));
            CPA16(sb + P1_KH + off, kh + idx);
            CPA16(sb + P1_KL + off, kl + idx);
        }
        CPA_COMMIT();
        CPA_WAIT0();
    }
    __syncthreads();

    float acc[2][4][4];
    #pragma unroll
    for (int m = 0; m < 2; m++)
        #pragma unroll
        for (int j = 0; j < 4; j++)
            #pragma unroll
            for (int e = 0; e < 4; e++) acc[m][j][e] = 0.0f;

    #pragma unroll
    for (int ks = 0; ks < 4; ks++) {
        const int k0 = ks * 16;
        uint32_t ah[2][4], al[2][4], bh[2][4], bl[2][4];
        #pragma unroll
        for (int m = 0; m < 2; m++) {
            uint32_t ra = SW128((uint32_t)((wm * 32 + m * 16 + lr) * 128 + (k0 + lc) * 2));
            ldsm_x4(ah[m][0], ah[m][1], ah[m][2], ah[m][3], sb + P1_QH + ra);
            ldsm_x4(al[m][0], al[m][1], al[m][2], al[m][3], sb + P1_QL + ra);
        }
        #pragma unroll
        for (int g = 0; g < 2; g++) {
            uint32_t rb = SW128((uint32_t)((wn * 32 + g * 16 + br) * 128 + (k0 + bc) * 2));
            ldsm_x4(bh[g][0], bh[g][1], bh[g][2], bh[g][3], sb + P1_KH + rb);
            ldsm_x4(bl[g][0], bl[g][1], bl[g][2], bl[g][3], sb + P1_KL + rb);
        }
        #pragma unroll
        for (int m = 0; m < 2; m++)
            #pragma unroll
            for (int j = 0; j < 4; j++) {
                uint32_t b0h = bh[j >> 1][(j & 1) * 2], b1h = bh[j >> 1][(j & 1) * 2 + 1];
                uint32_t b0l = bl[j >> 1][(j & 1) * 2], b1l = bl[j >> 1][(j & 1) * 2 + 1];
                mma_bf16(acc[m][j], ah[m][0], ah[m][1], ah[m][2], ah[m][3], b0h, b1h);
                mma_bf16(acc[m][j], al[m][0], al[m][1], al[m][2], al[m][3], b0h, b1h);
                mma_bf16(acc[m][j], ah[m][0], ah[m][1], ah[m][2], ah[m][3], b0l, b1l);
            }
    }

    float* zbuf = (float*)(sm + P1_ZB);
    #pragma unroll
    for (int j = 0; j < 4; j++) {
        float z0 = 0.0f, z1 = 0.0f;
        int cloc = wn * 32 + j * 8 + 2 * pair;
        int scol = bs * 128 + cloc;
        #pragma unroll
        for (int m = 0; m < 2; m++)
            #pragma unroll
            for (int rr = 0; rr < 2; rr++) {
                int trow = bt * 64 + wm * 32 + m * 16 + rr * 8 + quad;
                z0 += (scol     <= trow) ? fast_exp(acc[m][j][rr * 2])     : 0.0f;
                z1 += (scol + 1 <= trow) ? fast_exp(acc[m][j][rr * 2 + 1]) : 0.0f;
            }
        #pragma unroll
        for (int off = 4; off < 32; off <<= 1) {
            z0 += __shfl_xor_sync(0xffffffffu, z0, off);
            z1 += __shfl_xor_sync(0xffffffffu, z1, off);
        }
        if (quad == 0) {
            zbuf[wm * 128 + cloc]     = z0;
            zbuf[wm * 128 + cloc + 1] = z1;
        }
    }
    __syncthreads();
    if (tid < 128)
        g_z[((size_t)b * 32 + bt) * Tn + bs * 128 + tid] = zbuf[tid] + zbuf[128 + tid];
}

// ================= cmerge: sc[b][s] = 1 / sum_bt z (round-14 sequential form) =================
__global__ __launch_bounds__(256) void cmerge_kernel()
{
    int idx = blockIdx.x * 256 + threadIdx.x;
    int b = idx >> 11, s = idx & 2047;
    float z = 0.0f;
    for (int bt = s >> 6; bt < 32; bt++)
        z += g_z[((size_t)b * 32 + bt) * Tn + s];
    g_sc[idx] = 1.0f / z;
}

// ================= vscale: v' = sc[t] * v =================
__global__ __launch_bounds__(256) void vscale_kernel()
{
    int idx = blockIdx.x * 256 + threadIdx.x;
    int t2 = idx & 1023;
    int b  = idx >> 16;
    uint32_t hw = ((const uint32_t*)g_vh)[idx];
    uint32_t lw = ((const uint32_t*)g_vl)[idx];
    __nv_bfloat162 hb = *(__nv_bfloat162*)&hw;
    __nv_bfloat162 lb = *(__nv_bfloat162*)&lw;
    float sc0 = g_sc[b * Tn + 2 * t2];
    float sc1 = g_sc[b * Tn + 2 * t2 + 1];
    float v0 = (__low2float(hb)  + __low2float(lb))  * sc0;
    float v1 = (__high2float(hb) + __high2float(lb)) * sc1;
    uint32_t oh, ol;
    split2x2(v0, v1, oh, ol);
    ((uint32_t*)g_v2h)[idx] = oh;
    ((uint32_t*)g_v2l)[idx] = ol;
}

// ================= pass2: register P-frag reuse + split-wait cp.async =================
#define P2_QH 0
#define P2_QL 8192
#define P2_KH 16384
#define P2_KL 32768
#define P2_VH 49152
#define P2_VL 65536
#define P2_RED 81920
#define P2_SMEM (81920 + 64 * 66 * 4)
__global__ __launch_bounds__(256, 2) void pass2_kernel()
{
    const int bt = 31 - blockIdx.x;
    const int b  = blockIdx.y;
    const int sp = blockIdx.z;
    const int bsMax = ((bt + 1) * 64 - 1) >> 7;
    const int sBeg = sp * 8;
    const int sEnd = min(bsMax + 1, sBeg + 8);
    if (sBeg >= sEnd) return;

    extern __shared__ char sm[];
    const uint32_t sb = smem_u32(sm);
    const int tid = threadIdx.x, lane = tid & 31, wid = tid >> 5;
    const int wm = wid & 3, ws = wid >> 2;
    const int lr = lane & 15, lc = (lane & 16) >> 1;
    const int br = (lane & 7) + ((lane & 16) >> 1), bc = lane & 8;
    const int quad = lane >> 2, pair = lane & 3;

    {
        const uint4* qh = (const uint4*)(g_qh + ((size_t)b * Tn + bt * 64) * Hn);
        const uint4* ql = (const uint4*)(g_ql + ((size_t)b * Tn + bt * 64) * Hn);
        #pragma unroll
        for (int i = 0; i < 2; i++) {
            int idx = tid + i * 256;
            int row = idx >> 3, u = idx & 7;
            uint32_t off = SW128((uint32_t)(row * 128 + u * 16));
            CPA16(sb + P2_QH + off, qh + idx);
            CPA16(sb + P2_QL + off, ql + idx);
        }
        CPA_COMMIT();
    }

    const uint4* gKh = (const uint4*)(g_kh + (size_t)b * Tn * Hn);
    const uint4* gKl = (const uint4*)(g_kl + (size_t)b * Tn * Hn);
    const uint4* gVh4 = (const uint4*)(g_v2h + (size_t)b * Hn * Tn);
    const uint4* gVl4 = (const uint4*)(g_v2l + (size_t)b * Hn * Tn);

    float accO[8][4];
    #pragma unroll
    for (int g = 0; g < 8; g++)
        #pragma unroll
        for (int e = 0; e < 4; e++) accO[g][e] = 0.0f;

    for (int bs = sBeg; bs < sEnd; bs++) {
        __syncthreads();
        // K group
        #pragma unroll
        for (int i = 0; i < 4; i++) {
            int idx = tid + i * 256;
            int row = idx >> 3, u = idx & 7;
            uint32_t off = SW128((uint32_t)(row * 128 + u * 16));
            CPA16(sb + P2_KH + off, gKh + bs * 1024 + idx);
            CPA16(sb + P2_KL + off, gKl + bs * 1024 + idx);
        }
        CPA_COMMIT();
        // V group
        #pragma unroll
        for (int i = 0; i < 4; i++) {
            int idx = tid + i * 256;
            int d = idx >> 4, c = idx & 15;
            uint32_t off = SW256((uint32_t)(d * 256 + c * 16));
            CPA16(sb + P2_VH + off, gVh4 + (size_t)d * 256 + bs * 16 + c);
            CPA16(sb + P2_VL + off, gVl4 + (size_t)d * 256 + bs * 16 + c);
        }
        CPA_COMMIT();
        CPA_WAIT1();            // K (and Q on first iter) landed; V may still fly
        __syncthreads();

        float acc[8][4];
        #pragma unroll
        for (int j = 0; j < 8; j++)
            #pragma unroll
            for (int e = 0; e < 4; e++) acc[j][e] = 0.0f;
        #pragma unroll
        for (int ks = 0; ks < 4; ks++) {
            const int k0 = ks * 16;
            uint32_t ah[4], al[4];
            uint32_t ra = SW128((uint32_t)((wm * 16 + lr) * 128 + (k0 + lc) * 2));
            ldsm_x4(ah[0], ah[1], ah[2], ah[3], sb + P2_QH + ra);
            ldsm_x4(al[0], al[1], al[2], al[3], sb + P2_QL + ra);
            #pragma unroll
            for (int g16 = 0; g16 < 4; g16++) {
                uint32_t bh[4], bl[4];
                uint32_t rb = SW128((uint32_t)((ws * 64 + g16 * 16 + br) * 128 + (k0 + bc) * 2));
                ldsm_x4(bh[0], bh[1], bh[2], bh[3], sb + P2_KH + rb);
                ldsm_x4(bl[0], bl[1], bl[2], bl[3], sb + P2_KL + rb);
                #pragma unroll
                for (int jj = 0; jj < 2; jj++) {
                    int j = g16 * 2 + jj;
                    uint32_t b0h = bh[jj * 2], b1h = bh[jj * 2 + 1];
                    uint32_t b0l = bl[jj * 2], b1l = bl[jj * 2 + 1];
                    mma_bf16(acc[j], ah[0], ah[1], ah[2], ah[3], b0h, b1h);
                    mma_bf16(acc[j], al[0], al[1], al[2], al[3], b0h, b1h);
                    mma_bf16(acc[j], ah[0], ah[1], ah[2], ah[3], b0l, b1l);
                }
            }
        }
        CPA_WAIT0();            // V landed (overlapped with S-MMA above)
        __syncthreads();

        const int trow0 = bt * 64 + wm * 16 + quad;
        const int trow1 = trow0 + 8;
        #pragma unroll
        for (int kk = 0; kk < 4; kk++) {
            const int j0 = 2 * kk;
            uint32_t pah[4], pal[4];
            {
                int c0 = bs * 128 + ws * 64 + j0 * 8 + 2 * pair;
                float p0 = (c0     <= trow0) ? fast_exp(acc[j0][0]) : 0.0f;
                float p1 = (c0 + 1 <= trow0) ? fast_exp(acc[j0][1]) : 0.0f;
                split2x2(p0, p1, pah[0], pal[0]);
                p0 = (c0     <= trow1) ? fast_exp(acc[j0][2]) : 0.0f;
                p1 = (c0 + 1 <= trow1) ? fast_exp(acc[j0][3]) : 0.0f;
                split2x2(p0, p1, pah[1], pal[1]);
                int c1 = c0 + 8;
                p0 = (c1     <= trow0) ? fast_exp(acc[j0 + 1][0]) : 0.0f;
                p1 = (c1 + 1 <= trow0) ? fast_exp(acc[j0 + 1][1]) : 0.0f;
                split2x2(p0, p1, pah[2], pal[2]);
                p0 = (c1     <= trow1) ? fast_exp(acc[j0 + 1][2]) : 0.0f;
                p1 = (c1 + 1 <= trow1) ? fast_exp(acc[j0 + 1][3]) : 0.0f;
                split2x2(p0, p1, pah[3], pal[3]);
            }
            const int k0g = ws * 64 + kk * 16;
            #pragma unroll
            for (int g16 = 0; g16 < 4; g16++) {
                uint32_t vh[4], vl[4];
                uint32_t rb = SW256((uint32_t)((g16 * 16 + br) * 256 + (k0g + bc) * 2));
                ldsm_x4(vh[0], vh[1], vh[2], vh[3], sb + P2_VH + rb);
                ldsm_x4(vl[0], vl[1], vl[2], vl[3], sb + P2_VL + rb);
                #pragma unroll
                for (int gg = 0; gg < 2; gg++) {
                    int g = g16 * 2 + gg;
                    uint32_t b0h = vh[gg * 2], b1h = vh[gg * 2 + 1];
                    uint32_t b0l = vl[gg * 2], b1l = vl[gg * 2 + 1];
                    mma_bf16(accO[g], pah[0], pah[1], pah[2], pah[3], b0h, b1h);
                    mma_bf16(accO[g], pal[0], pal[1], pal[2], pal[3], b0h, b1h);
                    mma_bf16(accO[g], pah[0], pah[1], pah[2], pah[3], b0l, b1l);
                }
            }
        }
    }

    float* red = (float*)(sm + P2_RED);
    __syncthreads();
    if (ws == 1) {
        #pragma unroll
        for (int g = 0; g < 8; g++)
            #pragma unroll
            for (int rr = 0; rr < 2; rr++) {
                int row = wm * 16 + rr * 8 + quad;
                int col = g * 8 + 2 * pair;
                *(float2*)&red[row * 66 + col] =
                    make_float2(accO[g][rr * 2], accO[g][rr * 2 + 1]);
            }
    }
    __syncthreads();
    if (ws == 0) {
        #pragma unroll
        for (int g = 0; g < 8; g++)
            #pragma unroll
            for (int rr = 0; rr < 2; rr++) {
                int row = wm * 16 + rr * 8 + quad;
                int col = g * 8 + 2 * pair;
                float2 r = *(const float2*)&red[row * 66 + col];
                float2 v = make_float2(accO[g][rr * 2] + r.x, accO[g][rr * 2 + 1] + r.y);
                *(float2*)(g_opart + (((size_t)sp * Bn + b) * Tn + bt * 64 + row) * Hn + col) = v;
            }
    }
}

// ================= reduce =================
__global__ __launch_bounds__(256) void reduce_kernel(float* __restrict__ out)
{
    int idx = blockIdx.x * 256 + threadIdx.x;
    int d4 = idx & 15;
    int t  = (idx >> 4) & 2047;
    int b  = idx >> 15;
    float4 s = *(const float4*)(g_opart + (((size_t)b) * Tn + t) * Hn + d4 * 4);
    if (t >= 1024) {
        float4 v = *(const float4*)(g_opart + (((size_t)Bn + b) * Tn + t) * Hn + d4 * 4);
        s.x += v.x; s.y += v.y; s.z += v.z; s.w += v.w;
    }
    *(float4*)(out + ((size_t)b * Tn + t) * Hn + d4 * 4) = s;
}

extern "C" void kernel_launch(void* const* d_in, const int* in_sizes, int n_in,
                              void* d_out, int out_size)
{
    const float* x  = (const float*)d_in[0];
    const float* Wq = (const float*)d_in[1];
    const float* bq = (const float*)d_in[2];
    const float* Wk = (const float*)d_in[3];
    const float* bk = (const float*)d_in[4];
    const float* Wv = (const float*)d_in[5];
    const float* bv = (const float*)d_in[6];
    float* out = (float*)d_out;

    cudaFuncSetAttribute(qkv_kernel,   cudaFuncAttributeMaxDynamicSharedMemorySize, QK_SMEM);
    cudaFuncSetAttribute(pass1_kernel, cudaFuncAttributeMaxDynamicSharedMemorySize, P1_SMEM);
    cudaFuncSetAttribute(pass2_kernel, cudaFuncAttributeMaxDynamicSharedMemorySize, P2_SMEM);

    wsplit_kernel<<<384, 256>>>(Wq, Wk, Wv);
    qkv_kernel<<<768, 256, QK_SMEM>>>(x, bq, bk, bv);
    pass1_kernel<<<dim3(32, 16, 16), 256, P1_SMEM>>>();
    cmerge_kernel<<<128, 256>>>();
    vscale_kernel<<<4096, 256>>>();
    pass2_kernel<<<dim3(32, 16, 2), 256, P2_SMEM>>>();
    reduce_kernel<<<2048, 256>>>(out);
}